// round 15
// baseline (speedup 1.0000x reference)
#include <cuda_runtime.h>
#include <cuda_fp16.h>
#include <cstdint>

#define SEQ 32
#define EDIM 256
#define HDIM 256
#define GDIM 1024
#define ROWS 32
#define NCTAS 128
#define NTHREADS 512
#define NWARPS 16

#define XSW 132   // half2 words per row (264 halves): conflict-free
#define XS_WORDS (ROWS*XSW)                 // 4224 words per tile
#define CST_OFF  (3*XS_WORDS)               // Xs + 2 H buffers
#define SMEM_BYTES ((CST_OFF + 16*NTHREADS)*4)   // + cst[16][512] = 83,456 B

// fp16 B-fragment packed weights, uint4 pairs (nf 2j, 2j+1):
// index = ((w*32 + kc)*4 + j)*32 + lane ; w = warp 0..15 (64-col slice),
// kc 0..15 = X part (W_ih), 16..31 = H part (W_hh)
__device__ __align__(16) uint4 g_wpk4[NWARPS*32*4*32];
__device__ float g_bperm[GDIM];   // permuted bias (b_ih + b_hh)

__device__ __forceinline__ uint32_t f2h2(float lo, float hi) {
    __half2 p = __floats2half2_rn(lo, hi);
    return *(uint32_t*)&p;
}
__device__ __forceinline__ float tanh_fast(float x) {
    float r; asm("tanh.approx.f32 %0, %1;" : "=f"(r) : "f"(x)); return r;
}
__device__ __forceinline__ float sigmoid_fast(float x) {
    return fmaf(0.5f, tanh_fast(0.5f * x), 0.5f);
}

#define MMA_F16(d, a, b0, b1)                                               \
    asm volatile("mma.sync.aligned.m16n8k16.row.col.f32.f16.f16.f32 "      \
                 "{%0,%1,%2,%3}, {%4,%5,%6,%7}, {%8,%9}, {%0,%1,%2,%3};"    \
                 : "+f"((d)[0]), "+f"((d)[1]), "+f"((d)[2]), "+f"((d)[3])   \
                 : "r"((a)[0]), "r"((a)[1]), "r"((a)[2]), "r"((a)[3]),      \
                   "r"(b0), "r"(b1))

// =================== prep: permute + fp16 + fragment-pack ===================
__global__ void prep_kernel(const float* __restrict__ wih,
                            const float* __restrict__ whh,
                            const float* __restrict__ bih,
                            const float* __restrict__ bhh) {
    int i = blockIdx.x * blockDim.x + threadIdx.x;   // 0..65535
    if (i >= NWARPS*32*4*32) return;
    int lane = i & 31;
    int j    = (i >> 5) & 3;
    int kc   = (i >> 7) & 31;
    int w    = (i >> 12) & 15;
    int grp  = lane >> 2;
    int tg   = lane & 3;

    const float* W = (kc < 16) ? wih : whh;
    int kbase = (kc & 15)*16;

    uint4 v;
    #pragma unroll
    for (int h = 0; h < 2; ++h) {
        int nf = 2*j + h;
        int colperm = w*64 + nf*8 + grp;
        int unit = colperm >> 2, gate = colperm & 3;
        const float* wr = W + (gate*256 + unit)*256 + kbase;
        uint32_t b0 = f2h2(wr[2*tg], wr[2*tg + 1]);
        uint32_t b1 = f2h2(wr[2*tg + 8], wr[2*tg + 9]);
        if (h == 0) { v.x = b0; v.y = b1; } else { v.z = b0; v.w = b1; }
    }
    g_wpk4[i] = v;

    if (i < GDIM) {
        int u2 = i >> 2, g2 = i & 3;
        g_bperm[i] = bih[g2*256 + u2] + bhh[g2*256 + u2];
    }
}

// =================== fused LSTM (fp16 MMA, 2-deep weight prefetch) ===================
__global__ __launch_bounds__(NTHREADS, 1)
void lstm_fused_kernel(const float* __restrict__ x, float* __restrict__ out) {
    extern __shared__ uint32_t sm[];           // half2 words
    uint32_t* Xs   = sm;                        // [32][XSW]
    uint32_t* Hb   = sm + XS_WORDS;             // 2 x [32][XSW]
    float*    cstS = (float*)(sm + CST_OFF);    // [16][NTHREADS]

    const int tid  = threadIdx.x;
    const int lane = tid & 31;
    const int w    = tid >> 5;                  // 0..15, owns gate cols w*64..+63
    const int grp  = lane >> 2;
    const int tg   = lane & 3;
    const int tgl  = tg & 1;
    const int tgh  = tg >> 1;
    const long rowbase = (long)blockIdx.x * ROWS;

    for (int i = tid; i < XS_WORDS; i += NTHREADS) Hb[i] = 0u;
    #pragma unroll
    for (int i = 0; i < 16; ++i) cstS[i*NTHREADS + tid] = 0.0f;
    __syncthreads();

    const float* xbase = x + rowbase * (SEQ*EDIM);
    const uint4* wbase = g_wpk4 + ((size_t)w*32*4)*32 + lane;

    for (int s = 0; s < SEQ; ++s) {
        // ---- stage x_s tile [32][256] as fp16 half2 ----
        {
            const long srow = (long)s * EDIM;
            #pragma unroll
            for (int it = 0; it < 4; ++it) {
                int fi = tid + it * NTHREADS;
                int r  = fi >> 6;
                int cq = fi & 63;
                const float4 v = *((const float4*)(xbase + (long)r*(SEQ*EDIM) + srow) + cq);
                Xs[r*XSW + cq*2]     = f2h2(v.x, v.y);
                Xs[r*XSW + cq*2 + 1] = f2h2(v.z, v.w);
            }
        }
        __syncthreads();

        const uint32_t* Hcur = Hb + (s & 1) * XS_WORDS;
        __half*         Hnxt = (__half*)(Hb + ((s + 1) & 1) * XS_WORDS);
        const int nkc = (s == 0) ? 16 : 32;     // s=0: h=0, skip H part

        // accumulators, bias-initialized
        float d[2][8][4];
        #pragma unroll
        for (int nf = 0; nf < 8; ++nf) {
            int col = w*64 + nf*8 + 2*tg;
            float b0v = g_bperm[col], b1v = g_bperm[col + 1];
            d[0][nf][0] = b0v; d[0][nf][1] = b1v; d[0][nf][2] = b0v; d[0][nf][3] = b1v;
            d[1][nf][0] = b0v; d[1][nf][1] = b1v; d[1][nf][2] = b0v; d[1][nf][3] = b1v;
        }

        // ---- merged X+H mainloop: 3-slot weight ring (2-deep prefetch) ----
        uint4 wb[3][4];
        {
            #pragma unroll
            for (int j = 0; j < 4; ++j) wb[0][j] = wbase[j*32];
            const uint4* bp = wbase + (size_t)4*32;
            #pragma unroll
            for (int j = 0; j < 4; ++j) wb[1][j] = bp[j*32];
        }

        #pragma unroll 3
        for (int kc = 0; kc < nkc; ++kc) {
            const int cur = kc % 3;
            // prefetch weights kc+2 (2-deep)
            if (kc + 2 < nkc) {
                const int pre = (kc + 2) % 3;
                const uint4* bp = wbase + (size_t)(kc + 2)*4*32;
                #pragma unroll
                for (int j = 0; j < 4; ++j) wb[pre][j] = bp[j*32];
            }
            // a-fragments for kc (conflict-free scalar LDS, single-slot)
            const uint32_t* A = (kc < 16) ? Xs : Hcur;
            const int kw = (kc & 15)*8;
            uint32_t ab[8];
            #pragma unroll
            for (int mh = 0; mh < 2; ++mh) {
                int r0 = mh*16 + grp;
                ab[mh*4+0] = A[r0*XSW + kw + tg];
                ab[mh*4+1] = A[(r0+8)*XSW + kw + tg];
                ab[mh*4+2] = A[r0*XSW + kw + 4 + tg];
                ab[mh*4+3] = A[(r0+8)*XSW + kw + 4 + tg];
            }
            // compute kc
            #pragma unroll
            for (int j = 0; j < 4; ++j) {
                uint4 b = wb[cur][j];
                MMA_F16(d[0][2*j],   &ab[0], b.x, b.y);
                MMA_F16(d[1][2*j],   &ab[4], b.x, b.y);
                MMA_F16(d[0][2*j+1], &ab[0], b.z, b.w);
                MMA_F16(d[1][2*j+1], &ab[4], b.z, b.w);
            }
        }

        // ---- activation (tanh.approx), c-state in smem ----
        #pragma unroll
        for (int mh = 0; mh < 2; ++mh) {
            #pragma unroll
            for (int nf = 0; nf < 8; ++nf) {
                float c0 = d[mh][nf][0], c1 = d[mh][nf][1];
                float c2 = d[mh][nf][2], c3 = d[mh][nf][3];
                float x0 = __shfl_xor_sync(0xffffffffu, tgl ? c0 : c2, 1);
                float x1 = __shfl_xor_sync(0xffffffffu, tgl ? c1 : c3, 1);
                float gi = tgl ? x0 : c0;
                float gf = tgl ? x1 : c1;
                float gg = tgl ? c2 : x0;
                float go = tgl ? c3 : x1;
                int row = grp + 8*tgl + 16*mh;
                int u   = w*16 + 2*nf + tgh;        // global unit 0..255
                float cold = cstS[(mh*8 + nf)*NTHREADS + tid];
                float cv = sigmoid_fast(gf) * cold
                         + sigmoid_fast(gi) * tanh_fast(gg);
                cstS[(mh*8 + nf)*NTHREADS + tid] = cv;
                float h = sigmoid_fast(go) * tanh_fast(cv);
                Hnxt[row*(2*XSW) + u] = __float2half_rn(h);
                if (s == SEQ - 1) out[(rowbase + row)*HDIM + u] = h;
            }
        }
        __syncthreads();
    }
}

extern "C" void kernel_launch(void* const* d_in, const int* in_sizes, int n_in,
                              void* d_out, int out_size) {
    const float* x   = (const float*)d_in[0];
    const float* wih = (const float*)d_in[1];
    const float* whh = (const float*)d_in[2];
    const float* bih = (const float*)d_in[3];
    const float* bhh = (const float*)d_in[4];
    float* out = (float*)d_out;

    cudaFuncSetAttribute(lstm_fused_kernel,
                         cudaFuncAttributeMaxDynamicSharedMemorySize, SMEM_BYTES);

    prep_kernel<<<(NWARPS*32*4*32 + 255)/256, 256>>>(wih, whh, bih, bhh);
    lstm_fused_kernel<<<NCTAS, NTHREADS, SMEM_BYTES>>>(x, out);
}

// round 16
// speedup vs baseline: 1.4525x; 1.4525x over previous
#include <cuda_runtime.h>
#include <cuda_fp16.h>
#include <cstdint>

#define SEQ 32
#define EDIM 256
#define HDIM 256
#define GDIM 1024
#define ROWS 32
#define NCTAS 128
#define NTHREADS 512
#define NWARPS 16

#define XSW 136   // half2 words per row; 136 mod 32 = 8 -> conflict-free LDS.64 pairs
#define XS_WORDS (ROWS*XSW)
#define SMEM_BYTES (3*XS_WORDS*4)   // Xs + 2 H buffers = 52,224 B

// fp16 B-fragment packed weights, uint4 pairs (nf 2j, 2j+1):
// index = ((w*32 + kc)*4 + j)*32 + lane ; w = warp 0..15 (64-col slice),
// kc 0..15 = X part (W_ih), 16..31 = H part (W_hh)
__device__ __align__(16) uint4 g_wpk4[NWARPS*32*4*32];
__device__ float g_bperm[GDIM];   // permuted bias (b_ih + b_hh)

__device__ __forceinline__ uint32_t f2h2(float lo, float hi) {
    __half2 p = __floats2half2_rn(lo, hi);
    return *(uint32_t*)&p;
}
__device__ __forceinline__ float tanh_fast(float x) {
    float r; asm("tanh.approx.f32 %0, %1;" : "=f"(r) : "f"(x)); return r;
}
__device__ __forceinline__ float sigmoid_fast(float x) {
    return fmaf(0.5f, tanh_fast(0.5f * x), 0.5f);
}

#define MMA_F16(d, a, b0, b1)                                               \
    asm volatile("mma.sync.aligned.m16n8k16.row.col.f32.f16.f16.f32 "      \
                 "{%0,%1,%2,%3}, {%4,%5,%6,%7}, {%8,%9}, {%0,%1,%2,%3};"    \
                 : "+f"((d)[0]), "+f"((d)[1]), "+f"((d)[2]), "+f"((d)[3])   \
                 : "r"((a)[0]), "r"((a)[1]), "r"((a)[2]), "r"((a)[3]),      \
                   "r"(b0), "r"(b1))

// =================== prep: permute + fp16 + fragment-pack ===================
__global__ void prep_kernel(const float* __restrict__ wih,
                            const float* __restrict__ whh,
                            const float* __restrict__ bih,
                            const float* __restrict__ bhh) {
    int i = blockIdx.x * blockDim.x + threadIdx.x;   // 0..65535
    if (i >= NWARPS*32*4*32) return;
    int lane = i & 31;
    int j    = (i >> 5) & 3;
    int kc   = (i >> 7) & 31;
    int w    = (i >> 12) & 15;
    int grp  = lane >> 2;
    int tg   = lane & 3;

    const float* W = (kc < 16) ? wih : whh;
    int kbase = (kc & 15)*16;

    uint4 v;
    #pragma unroll
    for (int h = 0; h < 2; ++h) {
        int nf = 2*j + h;
        int colperm = w*64 + nf*8 + grp;
        int unit = colperm >> 2, gate = colperm & 3;
        const float* wr = W + (gate*256 + unit)*256 + kbase;
        uint32_t b0 = f2h2(wr[2*tg], wr[2*tg + 1]);
        uint32_t b1 = f2h2(wr[2*tg + 8], wr[2*tg + 9]);
        if (h == 0) { v.x = b0; v.y = b1; } else { v.z = b0; v.w = b1; }
    }
    g_wpk4[i] = v;

    if (i < GDIM) {
        int u2 = i >> 2, g2 = i & 3;
        g_bperm[i] = bih[g2*256 + u2] + bhh[g2*256 + u2];
    }
}

// =================== fused LSTM (fp16 MMA, k-paired smem, LDS.64 a-frags) ===================
__global__ __launch_bounds__(NTHREADS, 1)
void lstm_fused_kernel(const float* __restrict__ x, float* __restrict__ out) {
    extern __shared__ uint32_t sm[];           // half2 words
    uint32_t* Xs = sm;                          // [32][XSW], k-paired layout
    uint32_t* Hb = sm + XS_WORDS;               // 2 x [32][XSW], k-paired layout

    const int tid  = threadIdx.x;
    const int lane = tid & 31;
    const int w    = tid >> 5;                  // 0..15, owns gate cols w*64..+63
    const int grp  = lane >> 2;
    const int tg   = lane & 3;
    const int tgl  = tg & 1;
    const int tgh  = tg >> 1;
    const long rowbase = (long)blockIdx.x * ROWS;

    for (int i = tid; i < XS_WORDS; i += NTHREADS) Hb[i] = 0u;
    __syncthreads();

    float cst[2][8];
    #pragma unroll
    for (int a = 0; a < 2; ++a)
        #pragma unroll
        for (int b = 0; b < 8; ++b) cst[a][b] = 0.0f;

    const float* xbase = x + rowbase * (SEQ*EDIM);
    const uint4* wbase = g_wpk4 + ((size_t)w*32*4)*32 + lane;

    for (int s = 0; s < SEQ; ++s) {
        // ---- stage x_s tile [32][256] as fp16, k-paired word order ----
        // original word j in kc-group -> position 2*(j&3) + (j>>2)
        {
            const long srow = (long)s * EDIM;
            #pragma unroll
            for (int it = 0; it < 4; ++it) {
                int fi = tid + it * NTHREADS;
                int r  = fi >> 6;
                int cq = fi & 63;
                const float4 v = *((const float4*)(xbase + (long)r*(SEQ*EDIM) + srow) + cq);
                int kcg = cq >> 2;
                int j0  = 2*(cq & 3);                       // even j
                int p0  = 2*(j0 & 3) + (j0 >> 2);           // pos of word 2cq
                uint32_t* dst = &Xs[r*XSW + kcg*8];
                dst[p0]     = f2h2(v.x, v.y);               // word 2cq
                dst[p0 + 2] = f2h2(v.z, v.w);               // word 2cq+1 -> p0+2
            }
        }
        __syncthreads();

        const uint32_t* Hcur = Hb + (s & 1) * XS_WORDS;
        __half*         Hnxt = (__half*)(Hb + ((s + 1) & 1) * XS_WORDS);
        const int nkc = (s == 0) ? 16 : 32;     // s=0: h=0, skip H part

        // accumulators, bias-initialized
        float d[2][8][4];
        #pragma unroll
        for (int nf = 0; nf < 8; ++nf) {
            int col = w*64 + nf*8 + 2*tg;
            float b0v = g_bperm[col], b1v = g_bperm[col + 1];
            d[0][nf][0] = b0v; d[0][nf][1] = b1v; d[0][nf][2] = b0v; d[0][nf][3] = b1v;
            d[1][nf][0] = b0v; d[1][nf][1] = b1v; d[1][nf][2] = b0v; d[1][nf][3] = b1v;
        }

        // ---- merged X+H mainloop, 2-slot software pipeline ----
        uint4   wb[2][4];
        uint32_t ab[2][8];
        // prologue: fetch kc=0
        {
            #pragma unroll
            for (int j = 0; j < 4; ++j) wb[0][j] = wbase[j*32];
            #pragma unroll
            for (int mh = 0; mh < 2; ++mh) {
                int r0 = mh*16 + grp;
                uint2 v0 = *(const uint2*)(Xs + r0*XSW + 2*tg);
                uint2 v1 = *(const uint2*)(Xs + (r0+8)*XSW + 2*tg);
                ab[0][mh*4+0] = v0.x; ab[0][mh*4+2] = v0.y;
                ab[0][mh*4+1] = v1.x; ab[0][mh*4+3] = v1.y;
            }
        }

        #pragma unroll 2
        for (int kc = 0; kc < nkc; ++kc) {
            const int cur = kc & 1, nxt = cur ^ 1;
            // prefetch kc+1 (weights via LDG.128, a-frags via LDS.64)
            if (kc + 1 < nkc) {
                const uint4* bp = wbase + (size_t)(kc + 1)*4*32;
                #pragma unroll
                for (int j = 0; j < 4; ++j) wb[nxt][j] = bp[j*32];
                const uint32_t* A = (kc + 1 < 16) ? Xs : Hcur;
                const int kw = ((kc + 1) & 15)*8;
                #pragma unroll
                for (int mh = 0; mh < 2; ++mh) {
                    int r0 = mh*16 + grp;
                    uint2 v0 = *(const uint2*)(A + r0*XSW + kw + 2*tg);
                    uint2 v1 = *(const uint2*)(A + (r0+8)*XSW + kw + 2*tg);
                    ab[nxt][mh*4+0] = v0.x; ab[nxt][mh*4+2] = v0.y;
                    ab[nxt][mh*4+1] = v1.x; ab[nxt][mh*4+3] = v1.y;
                }
            }
            // compute kc
            #pragma unroll
            for (int j = 0; j < 4; ++j) {
                uint4 b = wb[cur][j];
                MMA_F16(d[0][2*j],   &ab[cur][0], b.x, b.y);
                MMA_F16(d[1][2*j],   &ab[cur][4], b.x, b.y);
                MMA_F16(d[0][2*j+1], &ab[cur][0], b.z, b.w);
                MMA_F16(d[1][2*j+1], &ab[cur][4], b.z, b.w);
            }
        }

        // ---- activation in registers (tanh.approx) ----
        #pragma unroll
        for (int mh = 0; mh < 2; ++mh) {
            #pragma unroll
            for (int nf = 0; nf < 8; ++nf) {
                float c0 = d[mh][nf][0], c1 = d[mh][nf][1];
                float c2 = d[mh][nf][2], c3 = d[mh][nf][3];
                float x0 = __shfl_xor_sync(0xffffffffu, tgl ? c0 : c2, 1);
                float x1 = __shfl_xor_sync(0xffffffffu, tgl ? c1 : c3, 1);
                float gi = tgl ? x0 : c0;
                float gf = tgl ? x1 : c1;
                float gg = tgl ? c2 : x0;
                float go = tgl ? c3 : x1;
                int row = grp + 8*tgl + 16*mh;
                int u   = w*16 + 2*nf + tgh;        // global unit 0..255
                float cv = sigmoid_fast(gf) * cst[mh][nf]
                         + sigmoid_fast(gi) * tanh_fast(gg);
                cst[mh][nf] = cv;
                float h = sigmoid_fast(go) * tanh_fast(cv);
                // k-paired store: word W=u>>1 (j=W&7, kcg=W>>3) -> pos 2*(j&3)+(j>>2)
                int Wd = u >> 1;
                int pj = 2*((Wd & 7) & 3) + ((Wd & 7) >> 2);
                int up = ((Wd & ~7) + pj)*2 + (u & 1);
                Hnxt[row*(2*XSW) + up] = __float2half_rn(h);
                if (s == SEQ - 1) out[(rowbase + row)*HDIM + u] = h;
            }
        }
        __syncthreads();
    }
}

extern "C" void kernel_launch(void* const* d_in, const int* in_sizes, int n_in,
                              void* d_out, int out_size) {
    const float* x   = (const float*)d_in[0];
    const float* wih = (const float*)d_in[1];
    const float* whh = (const float*)d_in[2];
    const float* bih = (const float*)d_in[3];
    const float* bhh = (const float*)d_in[4];
    float* out = (float*)d_out;

    cudaFuncSetAttribute(lstm_fused_kernel,
                         cudaFuncAttributeMaxDynamicSharedMemorySize, SMEM_BYTES);

    prep_kernel<<<(NWARPS*32*4*32 + 255)/256, 256>>>(wih, whh, bih, bhh);
    lstm_fused_kernel<<<NCTAS, NTHREADS, SMEM_BYTES>>>(x, out);
}

// round 17
// speedup vs baseline: 2.1495x; 1.4799x over previous
#include <cuda_runtime.h>
#include <cuda_fp16.h>
#include <cstdint>

#define SEQ 32
#define EDIM 256
#define HDIM 256
#define GDIM 1024
#define ROWS 32
#define NCTAS 128
#define NTHREADS 512
#define NWARPS 16

#define XSW 132   // half2 words per row (264 halves): conflict-free scalar LDS
#define XS_WORDS (ROWS*XSW)                 // 4224 words per tile
#define WSTG_WORD_OFF (3*XS_WORDS)          // weight stage ring after Xs + 2 H buffers
#define STG_U4 2048                          // uint4 per stage (16 warps x 4 x 32)
#define NSTG 4
#define SMEM_BYTES (WSTG_WORD_OFF*4 + NSTG*STG_U4*16)   // 50,688 + 131,072 = 181,760 B

// fp16 B-fragment packed weights, uint4 pairs (nf 2j, 2j+1):
// index = ((w*32 + kc)*4 + j)*32 + lane ; w = warp 0..15 (64-col slice),
// kc 0..15 = X part (W_ih), 16..31 = H part (W_hh)
__device__ __align__(16) uint4 g_wpk4[NWARPS*32*4*32];
__device__ float g_bperm[GDIM];   // permuted bias (b_ih + b_hh)

__device__ __forceinline__ uint32_t f2h2(float lo, float hi) {
    __half2 p = __floats2half2_rn(lo, hi);
    return *(uint32_t*)&p;
}
__device__ __forceinline__ float tanh_fast(float x) {
    float r; asm("tanh.approx.f32 %0, %1;" : "=f"(r) : "f"(x)); return r;
}
__device__ __forceinline__ float sigmoid_fast(float x) {
    return fmaf(0.5f, tanh_fast(0.5f * x), 0.5f);
}

#define MMA_F16(d, a, b0, b1)                                               \
    asm volatile("mma.sync.aligned.m16n8k16.row.col.f32.f16.f16.f32 "      \
                 "{%0,%1,%2,%3}, {%4,%5,%6,%7}, {%8,%9}, {%0,%1,%2,%3};"    \
                 : "+f"((d)[0]), "+f"((d)[1]), "+f"((d)[2]), "+f"((d)[3])   \
                 : "r"((a)[0]), "r"((a)[1]), "r"((a)[2]), "r"((a)[3]),      \
                   "r"(b0), "r"(b1))

#define CP_ASYNC16(dst, src) \
    asm volatile("cp.async.cg.shared.global [%0], [%1], 16;" :: "r"(dst), "l"(src) : "memory")
#define CP_COMMIT() asm volatile("cp.async.commit_group;" ::: "memory")
#define CP_WAIT3()  asm volatile("cp.async.wait_group 3;" ::: "memory")
#define CP_WAIT0()  asm volatile("cp.async.wait_group 0;" ::: "memory")

// =================== prep: permute + fp16 + fragment-pack ===================
__global__ void prep_kernel(const float* __restrict__ wih,
                            const float* __restrict__ whh,
                            const float* __restrict__ bih,
                            const float* __restrict__ bhh) {
    int i = blockIdx.x * blockDim.x + threadIdx.x;   // 0..65535
    if (i >= NWARPS*32*4*32) return;
    int lane = i & 31;
    int j    = (i >> 5) & 3;
    int kc   = (i >> 7) & 31;
    int w    = (i >> 12) & 15;
    int grp  = lane >> 2;
    int tg   = lane & 3;

    const float* W = (kc < 16) ? wih : whh;
    int kbase = (kc & 15)*16;

    uint4 v;
    #pragma unroll
    for (int h = 0; h < 2; ++h) {
        int nf = 2*j + h;
        int colperm = w*64 + nf*8 + grp;
        int unit = colperm >> 2, gate = colperm & 3;
        const float* wr = W + (gate*256 + unit)*256 + kbase;
        uint32_t b0 = f2h2(wr[2*tg], wr[2*tg + 1]);
        uint32_t b1 = f2h2(wr[2*tg + 8], wr[2*tg + 9]);
        if (h == 0) { v.x = b0; v.y = b1; } else { v.z = b0; v.w = b1; }
    }
    g_wpk4[i] = v;

    if (i < GDIM) {
        int u2 = i >> 2, g2 = i & 3;
        g_bperm[i] = bih[g2*256 + u2] + bhh[g2*256 + u2];
    }
}

// =================== fused LSTM (fp16 MMA, cp.async weight staging) ===================
__global__ __launch_bounds__(NTHREADS, 1)
void lstm_fused_kernel(const float* __restrict__ x, float* __restrict__ out) {
    extern __shared__ uint32_t sm[];           // half2 words
    uint32_t* Xs = sm;                          // [32][XSW]
    uint32_t* Hb = sm + XS_WORDS;               // 2 x [32][XSW]
    uint4*    Ws = (uint4*)(sm + WSTG_WORD_OFF);// weight stage ring [NSTG][STG_U4]

    const int tid  = threadIdx.x;
    const int lane = tid & 31;
    const int w    = tid >> 5;                  // 0..15, owns gate cols w*64..+63
    const int grp  = lane >> 2;
    const int tg   = lane & 3;
    const int tgl  = tg & 1;
    const int tgh  = tg >> 1;
    const long rowbase = (long)blockIdx.x * ROWS;

    for (int i = tid; i < XS_WORDS; i += NTHREADS) Hb[i] = 0u;
    __syncthreads();

    float cst[2][8];
    #pragma unroll
    for (int a = 0; a < 2; ++a)
        #pragma unroll
        for (int b = 0; b < 8; ++b) cst[a][b] = 0.0f;

    const float* xbase = x + rowbase * (SEQ*EDIM);
    const uint4* wbase = g_wpk4 + ((size_t)w*32*4)*32 + lane;   // this warp's slice, this lane

    // this warp's slice inside a stage: uint4 index (w*4 + j)*32 + lane
    const uint32_t stg_base_b = (uint32_t)__cvta_generic_to_shared(Ws);
    const uint32_t slice_b    = (uint32_t)(((w*4)*32 + lane) * 16);
    const uint4*   wsl        = Ws + (w*4)*32 + lane;           // generic-read side

    for (int s = 0; s < SEQ; ++s) {
        // ---- stage x_s tile [32][256] as fp16 half2 ----
        {
            const long srow = (long)s * EDIM;
            #pragma unroll
            for (int it = 0; it < 4; ++it) {
                int fi = tid + it * NTHREADS;
                int r  = fi >> 6;
                int cq = fi & 63;
                const float4 v = *((const float4*)(xbase + (long)r*(SEQ*EDIM) + srow) + cq);
                Xs[r*XSW + cq*2]     = f2h2(v.x, v.y);
                Xs[r*XSW + cq*2 + 1] = f2h2(v.z, v.w);
            }
        }
        __syncthreads();

        const uint32_t* Hcur = Hb + (s & 1) * XS_WORDS;
        __half*         Hnxt = (__half*)(Hb + ((s + 1) & 1) * XS_WORDS);
        const int nkc = (s == 0) ? 16 : 32;     // s=0: h=0, skip H part

        // accumulators, bias-initialized
        float d[2][8][4];
        #pragma unroll
        for (int nf = 0; nf < 8; ++nf) {
            int col = w*64 + nf*8 + 2*tg;
            float b0v = g_bperm[col], b1v = g_bperm[col + 1];
            d[0][nf][0] = b0v; d[0][nf][1] = b1v; d[0][nf][2] = b0v; d[0][nf][3] = b1v;
            d[1][nf][0] = b0v; d[1][nf][1] = b1v; d[1][nf][2] = b0v; d[1][nf][3] = b1v;
        }

        // ---- cp.async prologue: stages for kc = 0,1,2 (3 groups in flight) ----
        #pragma unroll
        for (int p = 0; p < 3; ++p) {
            const uint32_t dst = stg_base_b + (uint32_t)(p*STG_U4*16) + slice_b;
            const uint4*   src = wbase + (size_t)p*4*32;
            #pragma unroll
            for (int j = 0; j < 4; ++j)
                CP_ASYNC16(dst + j*512, src + j*32);
            CP_COMMIT();
        }

        // ---- merged X+H mainloop (weights via smem ring) ----
        #pragma unroll 2
        for (int kc = 0; kc < nkc; ++kc) {
            // issue prefetch for kc+3, always commit (empty group keeps count aligned)
            if (kc + 3 < nkc) {
                const int p = (kc + 3) & 3;
                const uint32_t dst = stg_base_b + (uint32_t)(p*STG_U4*16) + slice_b;
                const uint4*   src = wbase + (size_t)(kc + 3)*4*32;
                #pragma unroll
                for (int j = 0; j < 4; ++j)
                    CP_ASYNC16(dst + j*512, src + j*32);
            }
            CP_COMMIT();
            CP_WAIT3();   // group for kc complete

            // weights for kc from smem (4x LDS.128, conflict-free)
            const uint4* wp = wsl + (size_t)(kc & 3)*STG_U4;
            uint4 wv0 = wp[0*32], wv1 = wp[1*32], wv2 = wp[2*32], wv3 = wp[3*32];

            // a-fragments for kc (conflict-free scalar LDS)
            const uint32_t* A = (kc < 16) ? Xs : Hcur;
            const int kw = (kc & 15)*8;
            uint32_t ab[8];
            #pragma unroll
            for (int mh = 0; mh < 2; ++mh) {
                int r0 = mh*16 + grp;
                ab[mh*4+0] = A[r0*XSW + kw + tg];
                ab[mh*4+1] = A[(r0+8)*XSW + kw + tg];
                ab[mh*4+2] = A[r0*XSW + kw + 4 + tg];
                ab[mh*4+3] = A[(r0+8)*XSW + kw + 4 + tg];
            }

            MMA_F16(d[0][0], &ab[0], wv0.x, wv0.y);
            MMA_F16(d[1][0], &ab[4], wv0.x, wv0.y);
            MMA_F16(d[0][1], &ab[0], wv0.z, wv0.w);
            MMA_F16(d[1][1], &ab[4], wv0.z, wv0.w);
            MMA_F16(d[0][2], &ab[0], wv1.x, wv1.y);
            MMA_F16(d[1][2], &ab[4], wv1.x, wv1.y);
            MMA_F16(d[0][3], &ab[0], wv1.z, wv1.w);
            MMA_F16(d[1][3], &ab[4], wv1.z, wv1.w);
            MMA_F16(d[0][4], &ab[0], wv2.x, wv2.y);
            MMA_F16(d[1][4], &ab[4], wv2.x, wv2.y);
            MMA_F16(d[0][5], &ab[0], wv2.z, wv2.w);
            MMA_F16(d[1][5], &ab[4], wv2.z, wv2.w);
            MMA_F16(d[0][6], &ab[0], wv3.x, wv3.y);
            MMA_F16(d[1][6], &ab[4], wv3.x, wv3.y);
            MMA_F16(d[0][7], &ab[0], wv3.z, wv3.w);
            MMA_F16(d[1][7], &ab[4], wv3.z, wv3.w);
        }
        CP_WAIT0();   // drain before stages are rewritten next step

        // ---- activation in registers (tanh.approx) ----
        #pragma unroll
        for (int mh = 0; mh < 2; ++mh) {
            #pragma unroll
            for (int nf = 0; nf < 8; ++nf) {
                float c0 = d[mh][nf][0], c1 = d[mh][nf][1];
                float c2 = d[mh][nf][2], c3 = d[mh][nf][3];
                float x0 = __shfl_xor_sync(0xffffffffu, tgl ? c0 : c2, 1);
                float x1 = __shfl_xor_sync(0xffffffffu, tgl ? c1 : c3, 1);
                float gi = tgl ? x0 : c0;
                float gf = tgl ? x1 : c1;
                float gg = tgl ? c2 : x0;
                float go = tgl ? c3 : x1;
                int row = grp + 8*tgl + 16*mh;
                int u   = w*16 + 2*nf + tgh;        // global unit 0..255
                float cv = sigmoid_fast(gf) * cst[mh][nf]
                         + sigmoid_fast(gi) * tanh_fast(gg);
                cst[mh][nf] = cv;
                float h = sigmoid_fast(go) * tanh_fast(cv);
                Hnxt[row*(2*XSW) + u] = __float2half_rn(h);
                if (s == SEQ - 1) out[(rowbase + row)*HDIM + u] = h;
            }
        }
        __syncthreads();
    }
}

extern "C" void kernel_launch(void* const* d_in, const int* in_sizes, int n_in,
                              void* d_out, int out_size) {
    const float* x   = (const float*)d_in[0];
    const float* wih = (const float*)d_in[1];
    const float* whh = (const float*)d_in[2];
    const float* bih = (const float*)d_in[3];
    const float* bhh = (const float*)d_in[4];
    float* out = (float*)d_out;

    cudaFuncSetAttribute(lstm_fused_kernel,
                         cudaFuncAttributeMaxDynamicSharedMemorySize, SMEM_BYTES);

    prep_kernel<<<(NWARPS*32*4*32 + 255)/256, 256>>>(wih, whh, bih, bhh);
    lstm_fused_kernel<<<NCTAS, NTHREADS, SMEM_BYTES>>>(x, out);
}